// round 7
// baseline (speedup 1.0000x reference)
#include <cuda_runtime.h>

#define HIDDEN   64
#define NTHREADS 128     // 4 warps; thread = (unit j, k-half); handles BOTH batches

// ---------- packed f32x2 helpers ----------
__device__ __forceinline__ unsigned long long ffma2(unsigned long long a,
                                                    unsigned long long b,
                                                    unsigned long long c) {
    unsigned long long d;
    asm("fma.rn.f32x2 %0, %1, %2, %3;" : "=l"(d) : "l"(a), "l"(b), "l"(c));
    return d;
}
__device__ __forceinline__ unsigned long long fadd2(unsigned long long a,
                                                    unsigned long long b) {
    unsigned long long d;
    asm("add.rn.f32x2 %0, %1, %2;" : "=l"(d) : "l"(a), "l"(b));
    return d;
}
__device__ __forceinline__ unsigned long long pack2(float lo, float hi) {
    unsigned long long r;
    asm("mov.b64 %0, {%1, %2};" : "=l"(r) : "f"(lo), "f"(hi));
    return r;
}
__device__ __forceinline__ float2 unpack2(unsigned long long v) {
    float2 r;
    asm("mov.b64 {%0, %1}, %2;" : "=f"(r.x), "=f"(r.y) : "l"(v));
    return r;
}
__device__ __forceinline__ float tanh_approx(float x) {   // 1 MUFU
    float r; asm("tanh.approx.f32 %0, %1;" : "=f"(r) : "f"(x)); return r;
}

__global__ void __launch_bounds__(NTHREADS, 1)
gru_scan_kernel(const float* __restrict__ x,
                const float* __restrict__ W_ih,
                const float* __restrict__ W_hh,
                const float* __restrict__ b_ih,
                const float* __restrict__ b_hh,
                const float* __restrict__ W_fc,
                const float* __restrict__ b_fc,
                float* __restrict__ out,
                int Btotal, int T)
{
    __shared__ __align__(16) float h_sh[2][2][HIDDEN];   // [parity][batch][j]
    __shared__ float red_sh[2][4];

    const int tid  = threadIdx.x;
    const int wg   = tid / 32;               // warp 0..3
    const int lane = tid % 32;
    const int j    = wg * 16 + (lane & 15);  // hidden unit
    const int half = lane >> 4;              // k-half; partner lane^16
    const int bA   = blockIdx.x * 2;
    const int bB   = bA + 1;

    // ---- all 3 gate half-rows in registers: 3 x 16 packed f32x2 (96 regs) ----
    unsigned long long wreg[3][16];
    #pragma unroll
    for (int g = 0; g < 3; g++) {
        const float4* row = reinterpret_cast<const float4*>(
            W_hh + (g * HIDDEN + j) * HIDDEN + half * 32);
        #pragma unroll
        for (int i = 0; i < 8; i++) {
            float4 v = row[i];
            wreg[g][2 * i]     = pack2(v.x, v.y);
            wreg[g][2 * i + 1] = pack2(v.z, v.w);
        }
    }

    // per-unit constants (shared by both batch streams)
    const float wr_h = 0.5f * W_ih[j];
    const float br_h = 0.5f * (b_ih[j] + b_hh[j]);
    const float wz_h = 0.5f * W_ih[HIDDEN + j];
    const float bz_h = 0.5f * (b_ih[HIDDEN + j] + b_hh[HIDDEN + j]);
    const float wn   = W_ih[2 * HIDDEN + j];
    const float bihn = b_ih[2 * HIDDEN + j];
    const float bhhn = b_hh[2 * HIDDEN + j];
    const float wfc  = W_fc[j];
    const float bfc  = __ldg(b_fc);

    const float* xA = x + (size_t)((bA < Btotal) ? bA : 0) * T;
    const float* xB = x + (size_t)((bB < Btotal) ? bB : 0) * T;
    float xvA = __ldg(xA), xvB = __ldg(xB);
    float hAo = 0.0f, hBo = 0.0f;

    if (half == 0) { h_sh[0][0][j] = 0.0f; h_sh[0][1][j] = 0.0f; }
    __syncthreads();

    for (int t = 0; t < T; t++) {
        const int par = t & 1, nxt = par ^ 1;
        const ulonglong2* a2 = reinterpret_cast<const ulonglong2*>(h_sh[par][0] + half * 32);
        const ulonglong2* b2 = reinterpret_cast<const ulonglong2*>(h_sh[par][1] + half * 32);

        int tn = (t + 1 < T) ? t + 1 : T - 1;
        float xnA = __ldg(xA + tn);
        float xnB = __ldg(xB + tn);
        // x-terms (off the h-dependent chain)
        float arhA = fmaf(xvA, wr_h, br_h), azhA = fmaf(xvA, wz_h, bz_h), ainA = fmaf(xvA, wn, bihn);
        float arhB = fmaf(xvB, wr_h, br_h), azhB = fmaf(xvB, wz_h, bz_h), ainB = fmaf(xvB, wn, bihn);

        // ======== batch A: load h-half, 3 half-dots ========
        float dA[3];
        {
            unsigned long long hv[16];
            #pragma unroll
            for (int i = 0; i < 8; i++) {
                ulonglong2 v = a2[i];
                hv[2 * i] = v.x; hv[2 * i + 1] = v.y;
            }
            #pragma unroll
            for (int g = 0; g < 3; g++) {
                unsigned long long q0, q1, q2, q3;
                q0 = ffma2(wreg[g][0], hv[0], 0ull);
                q1 = ffma2(wreg[g][1], hv[1], 0ull);
                q2 = ffma2(wreg[g][2], hv[2], 0ull);
                q3 = ffma2(wreg[g][3], hv[3], 0ull);
                #pragma unroll
                for (int i = 1; i < 4; i++) {
                    q0 = ffma2(wreg[g][4 * i],     hv[4 * i],     q0);
                    q1 = ffma2(wreg[g][4 * i + 1], hv[4 * i + 1], q1);
                    q2 = ffma2(wreg[g][4 * i + 2], hv[4 * i + 2], q2);
                    q3 = ffma2(wreg[g][4 * i + 3], hv[4 * i + 3], q3);
                }
                float2 sp = unpack2(fadd2(fadd2(q0, q1), fadd2(q2, q3)));
                dA[g] = sp.x + sp.y;
            }
        }

        // ======== batch B: load h-half, 3 half-dots ========
        float dB[3];
        {
            unsigned long long hv[16];
            #pragma unroll
            for (int i = 0; i < 8; i++) {
                ulonglong2 v = b2[i];
                hv[2 * i] = v.x; hv[2 * i + 1] = v.y;
            }
            #pragma unroll
            for (int g = 0; g < 3; g++) {
                unsigned long long q0, q1, q2, q3;
                q0 = ffma2(wreg[g][0], hv[0], 0ull);
                q1 = ffma2(wreg[g][1], hv[1], 0ull);
                q2 = ffma2(wreg[g][2], hv[2], 0ull);
                q3 = ffma2(wreg[g][3], hv[3], 0ull);
                #pragma unroll
                for (int i = 1; i < 4; i++) {
                    q0 = ffma2(wreg[g][4 * i],     hv[4 * i],     q0);
                    q1 = ffma2(wreg[g][4 * i + 1], hv[4 * i + 1], q1);
                    q2 = ffma2(wreg[g][4 * i + 2], hv[4 * i + 2], q2);
                    q3 = ffma2(wreg[g][4 * i + 3], hv[4 * i + 3], q3);
                }
                float2 sp = unpack2(fadd2(fadd2(q0, q1), fadd2(q2, q3)));
                dB[g] = sp.x + sp.y;
            }
        }

        // ======== half exchange (intra-warp, no barrier) ========
        float drA = dA[0] + __shfl_xor_sync(0xffffffffu, dA[0], 16);
        float dzA = dA[1] + __shfl_xor_sync(0xffffffffu, dA[1], 16);
        float dnA = dA[2] + __shfl_xor_sync(0xffffffffu, dA[2], 16);
        float drB = dB[0] + __shfl_xor_sync(0xffffffffu, dB[0], 16);
        float dzB = dB[1] + __shfl_xor_sync(0xffffffffu, dB[1], 16);
        float dnB = dB[2] + __shfl_xor_sync(0xffffffffu, dB[2], 16);

        // ======== nonlinearity + update (A and B streams interleave) ========
        float taurA = tanh_approx(fmaf(0.5f, drA, arhA));
        float taurB = tanh_approx(fmaf(0.5f, drB, arhB));
        float tauzA = tanh_approx(fmaf(0.5f, dzA, azhA));
        float tauzB = tanh_approx(fmaf(0.5f, dzB, azhB));
        float dnbA = dnA + bhhn;
        float dnbB = dnB + bhhn;
        float nvA  = tanh_approx(fmaf(taurA, 0.5f * dnbA, fmaf(0.5f, dnbA, ainA)));
        float nvB  = tanh_approx(fmaf(taurB, 0.5f * dnbB, fmaf(0.5f, dnbB, ainB)));
        float ddA = hAo - nvA;
        float ddB = hBo - nvB;
        hAo = fmaf(tauzA, 0.5f * ddA, fmaf(0.5f, ddA, nvA));   // n + z*(h-n)
        hBo = fmaf(tauzB, 0.5f * ddB, fmaf(0.5f, ddB, nvB));

        if (half == 0) {
            h_sh[nxt][0][j] = hAo;
            h_sh[nxt][1][j] = hBo;
        }
        __syncthreads();     // one barrier serves both batches; drains STS
        xvA = xnA; xvB = xnB;
    }

    // ---- epilogue: out[b] = h . W_fc + b_fc ----
    float vA = (half == 0) ? hAo * wfc : 0.0f;
    float vB = (half == 0) ? hBo * wfc : 0.0f;
    #pragma unroll
    for (int o = 16; o > 0; o >>= 1) {
        vA += __shfl_xor_sync(0xffffffffu, vA, o);
        vB += __shfl_xor_sync(0xffffffffu, vB, o);
    }
    if (lane == 0) { red_sh[0][wg] = vA; red_sh[1][wg] = vB; }
    __syncthreads();
    if (tid == 0) {
        float sA = red_sh[0][0] + red_sh[0][1] + red_sh[0][2] + red_sh[0][3] + bfc;
        float sB = red_sh[1][0] + red_sh[1][1] + red_sh[1][2] + red_sh[1][3] + bfc;
        if (bA < Btotal) out[bA] = sA;
        if (bB < Btotal) out[bB] = sB;
    }
}

extern "C" void kernel_launch(void* const* d_in, const int* in_sizes, int n_in,
                              void* d_out, int out_size)
{
    const float* x    = (const float*)d_in[0];
    const float* W_ih = (const float*)d_in[1];
    const float* W_hh = (const float*)d_in[2];
    const float* b_ih = (const float*)d_in[3];
    const float* b_hh = (const float*)d_in[4];
    const float* W_fc = (const float*)d_in[5];
    const float* b_fc = (const float*)d_in[6];

    int B = out_size;                 // 256
    int T = in_sizes[0] / B;          // 3000
    int grid = (B + 1) / 2;           // 128 CTAs -> 1 per SM, 2 batches each

    gru_scan_kernel<<<grid, NTHREADS>>>(x, W_ih, W_hh, b_ih, b_hh, W_fc, b_fc,
                                        (float*)d_out, B, T);
}